// round 2
// baseline (speedup 1.0000x reference)
#include <cuda_runtime.h>
#include <math.h>
#include <stdint.h>

// Problem constants (dataset-fixed shapes)
#define B_SZ   1024
#define N_SZ   8192
#define M_C    3000        // N_COMMON
#define MP     3008        // padded M (multiple of 16, zero-filled tail)
#define EPS_B  1e-8f

// ---------------- scratch (no runtime allocation allowed) ----------------
__device__ float g_y1c[B_SZ * MP];
__device__ float g_y2c[B_SZ * MP];
__device__ float g_sq1[B_SZ];
__device__ float g_sq2[B_SZ];
__device__ float g_xmin;
__device__ float g_xmax;

// ---------------- kernel 1: batch-scalar min/max ----------------
__global__ void minmax_kernel(const float* __restrict__ x, int B, int N) {
    __shared__ float smin[32], smax[32];
    int tid = threadIdx.x;
    float mn = INFINITY, mx = -INFINITY;
    for (int b = tid; b < B; b += blockDim.x) {
        mn = fminf(mn, x[(size_t)b * N]);
        mx = fmaxf(mx, x[(size_t)b * N + (N - 1)]);
    }
    #pragma unroll
    for (int o = 16; o > 0; o >>= 1) {
        mn = fminf(mn, __shfl_xor_sync(0xffffffffu, mn, o));
        mx = fmaxf(mx, __shfl_xor_sync(0xffffffffu, mx, o));
    }
    if ((tid & 31) == 0) { smin[tid >> 5] = mn; smax[tid >> 5] = mx; }
    __syncthreads();
    if (tid < 32) {
        int nw = (blockDim.x + 31) >> 5;
        mn = (tid < nw) ? smin[tid] : INFINITY;
        mx = (tid < nw) ? smax[tid] : -INFINITY;
        #pragma unroll
        for (int o = 16; o > 0; o >>= 1) {
            mn = fminf(mn, __shfl_xor_sync(0xffffffffu, mn, o));
            mx = fmaxf(mx, __shfl_xor_sync(0xffffffffu, mx, o));
        }
        if (tid == 0) { g_xmin = mn; g_xmax = mx; }
    }
}

// ---------------- kernel 2: interpolation + per-row sq means ----------------
// One block per batch row. x row cached in shared (32KB), binary search per
// common point, gather+lerp y1/y2, write padded scratch + reduce sums.
__global__ __launch_bounds__(256) void interp_kernel(
    const float* __restrict__ x,
    const float* __restrict__ y1,
    const float* __restrict__ y2,
    int N)
{
    __shared__ float sx[N_SZ];
    __shared__ float red1[8], red2[8];

    int b   = blockIdx.x;
    int tid = threadIdx.x;

    const float* xr  = x  + (size_t)b * N;
    const float* y1r = y1 + (size_t)b * N;
    const float* y2r = y2 + (size_t)b * N;

    // coalesced vector load of the sorted x row
    const float4* xr4 = (const float4*)xr;
    for (int i = tid; i < N / 4; i += blockDim.x)
        ((float4*)sx)[i] = xr4[i];
    __syncthreads();

    const float xmin  = g_xmin;
    const float range = g_xmax - xmin;
    const float x0 = sx[0];
    const float xN = sx[N - 1];

    float s1 = 0.f, s2 = 0.f;

    for (int m = tid; m < MP; m += blockDim.x) {
        float v1 = 0.f, v2 = 0.f;
        if (m < M_C) {
            float t  = (m == M_C - 1) ? 1.0f : (float)m * (1.0f / (float)(M_C - 1));
            float xc = xmin + t * range;
            if (xc >= x0 && xc <= xN) {
                // lower_bound: first idx with sx[idx] >= xc  (searchsorted side='left')
                int lo = 0, hi = N;
                #pragma unroll 1
                while (lo < hi) {
                    int mid = (lo + hi) >> 1;
                    if (sx[mid] < xc) lo = mid + 1; else hi = mid;
                }
                int li = min(max(lo - 1, 0), N - 2);
                int hiI = min(lo, N - 1);
                float xl = sx[li], xh = sx[hiI];
                float denom = xh - xl;
                if (denom == 0.f) denom = 1.f;
                float w = (xc - xl) / (denom + 1e-9f);
                w = fminf(fmaxf(w, 0.f), 1.f);
                float a1 = __ldg(y1r + li), b1 = __ldg(y1r + hiI);
                float a2 = __ldg(y2r + li), b2 = __ldg(y2r + hiI);
                v1 = a1 + w * (b1 - a1);
                v2 = a2 + w * (b2 - a2);
            }
        }
        g_y1c[(size_t)b * MP + m] = v1;
        g_y2c[(size_t)b * MP + m] = v2;
        s1 += v1 * v1;
        s2 += v2 * v2;
    }

    // block reduce
    #pragma unroll
    for (int o = 16; o > 0; o >>= 1) {
        s1 += __shfl_xor_sync(0xffffffffu, s1, o);
        s2 += __shfl_xor_sync(0xffffffffu, s2, o);
    }
    if ((tid & 31) == 0) { red1[tid >> 5] = s1; red2[tid >> 5] = s2; }
    __syncthreads();
    if (tid == 0) {
        float t1 = 0.f, t2 = 0.f;
        #pragma unroll
        for (int w = 0; w < 8; w++) { t1 += red1[w]; t2 += red2[w]; }
        g_sq1[b] = t1 * (1.0f / (float)M_C);
        g_sq2[b] = t2 * (1.0f / (float)M_C);
    }
}

// ---------------- kernel 3: fp32 SIMT GEMM + fused loss epilogue ----------------
// C[i][j] = dot(y1c[i,:], y2c[j,:]); out = sqrt(2*max(sq1[i]+sq2[j]-2*C/M,0)/(sq1[i]+sq2[i]+eps))
// Tiles: BM=128, BN=64, BK=16; 256 threads; thread tile 8x4; double-buffered smem.
#define BM 128
#define BN 64
#define BK 16
#define AS_STRIDE (BM + 4)   // 132 (keeps float4 alignment, dodges worst conflicts)
#define BS_STRIDE (BN + 4)   // 68

__global__ __launch_bounds__(256) void gemm_loss_kernel(float* __restrict__ out, int B) {
    __shared__ float As[2][BK][AS_STRIDE];
    __shared__ float Bs[2][BK][BS_STRIDE];

    const int tid  = threadIdx.x;
    const int tx   = tid & 15;   // 0..15 -> 4 cols each
    const int ty   = tid >> 4;   // 0..15 -> 8 rows each
    const int brow = blockIdx.y;
    const int bcol = blockIdx.x;

    const float* A  = g_y1c + (size_t)brow * BM * MP;
    const float* Bp = g_y2c + (size_t)bcol * BN * MP;

    // global-load assignment: each thread loads one float4 from 3 tiles
    const int gr  = tid >> 2;        // 0..63 : row within tile
    const int gk4 = (tid & 3) * 4;   // 0..12 : k offset (float4)

    float acc[8][4];
    #pragma unroll
    for (int r = 0; r < 8; r++)
        #pragma unroll
        for (int c = 0; c < 4; c++) acc[r][c] = 0.f;

    float4 a_reg0, a_reg1, b_reg;

    // prologue: load tile 0
    a_reg0 = *(const float4*)(A  + (size_t)gr        * MP + gk4);
    a_reg1 = *(const float4*)(A  + (size_t)(gr + 64) * MP + gk4);
    b_reg  = *(const float4*)(Bp + (size_t)gr        * MP + gk4);
    #pragma unroll
    for (int i = 0; i < 4; i++) {
        As[0][gk4 + i][gr]      = ((const float*)&a_reg0)[i];
        As[0][gk4 + i][gr + 64] = ((const float*)&a_reg1)[i];
        Bs[0][gk4 + i][gr]      = ((const float*)&b_reg)[i];
    }
    __syncthreads();

    const int nkb = MP / BK;   // 188
    for (int kb = 0; kb < nkb; kb++) {
        const int buf = kb & 1;
        if (kb + 1 < nkb) {
            int k0 = (kb + 1) * BK;
            a_reg0 = *(const float4*)(A  + (size_t)gr        * MP + k0 + gk4);
            a_reg1 = *(const float4*)(A  + (size_t)(gr + 64) * MP + k0 + gk4);
            b_reg  = *(const float4*)(Bp + (size_t)gr        * MP + k0 + gk4);
        }
        #pragma unroll
        for (int k = 0; k < BK; k++) {
            float4 a0 = *(const float4*)&As[buf][k][ty * 8];
            float4 a1 = *(const float4*)&As[buf][k][ty * 8 + 4];
            float4 bb = *(const float4*)&Bs[buf][k][tx * 4];
            float av[8] = {a0.x, a0.y, a0.z, a0.w, a1.x, a1.y, a1.z, a1.w};
            float bv[4] = {bb.x, bb.y, bb.z, bb.w};
            #pragma unroll
            for (int r = 0; r < 8; r++)
                #pragma unroll
                for (int c = 0; c < 4; c++)
                    acc[r][c] = fmaf(av[r], bv[c], acc[r][c]);
        }
        if (kb + 1 < nkb) {
            const int nb = buf ^ 1;
            #pragma unroll
            for (int i = 0; i < 4; i++) {
                As[nb][gk4 + i][gr]      = ((const float*)&a_reg0)[i];
                As[nb][gk4 + i][gr + 64] = ((const float*)&a_reg1)[i];
                Bs[nb][gk4 + i][gr]      = ((const float*)&b_reg)[i];
            }
        }
        __syncthreads();
    }

    // epilogue: fused loss
    const float inv_m = 1.0f / (float)M_C;
    const int i0 = brow * BM + ty * 8;
    const int j0 = bcol * BN + tx * 4;
    float sq2v[4];
    #pragma unroll
    for (int c = 0; c < 4; c++) sq2v[c] = g_sq2[j0 + c];
    #pragma unroll
    for (int r = 0; r < 8; r++) {
        int i = i0 + r;
        float s1   = g_sq1[i];
        float base = s1 + g_sq2[i] + EPS_B;   // NOTE: both indexed by i (reference quirk)
        float4 o;
        #pragma unroll
        for (int c = 0; c < 4; c++) {
            float cross = acc[r][c] * inv_m;
            float diff  = fmaxf(s1 + sq2v[c] - 2.0f * cross, 0.f);
            ((float*)&o)[c] = sqrtf(2.0f * diff / base);
        }
        *(float4*)(out + (size_t)i * B + j0) = o;
    }
}

// ---------------- launch ----------------
extern "C" void kernel_launch(void* const* d_in, const int* in_sizes, int n_in,
                              void* d_out, int out_size) {
    const float* x  = (const float*)d_in[0];
    const float* y1 = (const float*)d_in[1];
    const float* y2 = (const float*)d_in[2];
    float* out = (float*)d_out;

    // out is [B, B] -> exact integer sqrt
    int B = 1;
    while ((long long)(B + 1) * (B + 1) <= (long long)out_size) B++;
    int N = in_sizes[0] / B;

    minmax_kernel<<<1, 1024>>>(x, B, N);
    interp_kernel<<<B, 256>>>(x, y1, y2, N);
    dim3 grid(B / BN, B / BM);
    gemm_loss_kernel<<<grid, 256>>>(out, B);
}

// round 3
// speedup vs baseline: 2.5894x; 2.5894x over previous
#include <cuda_runtime.h>
#include <cuda_bf16.h>
#include <math.h>
#include <stdint.h>

// Problem constants (dataset-fixed shapes)
#define B_SZ   1024
#define N_SZ   8192
#define M_C    3000        // N_COMMON
#define MP     3008        // padded M (multiple of 32, zero-filled tail)
#define EPS_B  1e-8f

// ---------------- scratch (no runtime allocation allowed) ----------------
__device__ __align__(16) __nv_bfloat16 g_y1c[B_SZ * MP];
__device__ __align__(16) __nv_bfloat16 g_y2c[B_SZ * MP];
__device__ float g_sq1[B_SZ];
__device__ float g_sq2[B_SZ];
__device__ float g_xmin;
__device__ float g_xmax;

// ---------------- kernel 1: batch-scalar min/max ----------------
__global__ void minmax_kernel(const float* __restrict__ x, int B, int N) {
    __shared__ float smin[32], smax[32];
    int tid = threadIdx.x;
    float mn = INFINITY, mx = -INFINITY;
    for (int b = tid; b < B; b += blockDim.x) {
        mn = fminf(mn, x[(size_t)b * N]);
        mx = fmaxf(mx, x[(size_t)b * N + (N - 1)]);
    }
    #pragma unroll
    for (int o = 16; o > 0; o >>= 1) {
        mn = fminf(mn, __shfl_xor_sync(0xffffffffu, mn, o));
        mx = fmaxf(mx, __shfl_xor_sync(0xffffffffu, mx, o));
    }
    if ((tid & 31) == 0) { smin[tid >> 5] = mn; smax[tid >> 5] = mx; }
    __syncthreads();
    if (tid < 32) {
        int nw = (blockDim.x + 31) >> 5;
        mn = (tid < nw) ? smin[tid] : INFINITY;
        mx = (tid < nw) ? smax[tid] : -INFINITY;
        #pragma unroll
        for (int o = 16; o > 0; o >>= 1) {
            mn = fminf(mn, __shfl_xor_sync(0xffffffffu, mn, o));
            mx = fmaxf(mx, __shfl_xor_sync(0xffffffffu, mx, o));
        }
        if (tid == 0) { g_xmin = mn; g_xmax = mx; }
    }
}

// ---------------- kernel 2: interpolation + per-row sq means ----------------
// One block per batch row. x row cached in shared (32KB), binary search per
// common point, gather+lerp y1/y2, write bf16 scratch + fp32 sq sums.
__global__ __launch_bounds__(256) void interp_kernel(
    const float* __restrict__ x,
    const float* __restrict__ y1,
    const float* __restrict__ y2,
    int N)
{
    __shared__ float sx[N_SZ];
    __shared__ float red1[8], red2[8];

    int b   = blockIdx.x;
    int tid = threadIdx.x;

    const float* xr  = x  + (size_t)b * N;
    const float* y1r = y1 + (size_t)b * N;
    const float* y2r = y2 + (size_t)b * N;

    const float4* xr4 = (const float4*)xr;
    for (int i = tid; i < N / 4; i += blockDim.x)
        ((float4*)sx)[i] = xr4[i];
    __syncthreads();

    const float xmin  = g_xmin;
    const float range = g_xmax - xmin;
    const float x0 = sx[0];
    const float xN = sx[N - 1];

    float s1 = 0.f, s2 = 0.f;

    for (int m = tid; m < MP; m += blockDim.x) {
        float v1 = 0.f, v2 = 0.f;
        if (m < M_C) {
            float t  = (m == M_C - 1) ? 1.0f : (float)m * (1.0f / (float)(M_C - 1));
            float xc = xmin + t * range;
            if (xc >= x0 && xc <= xN) {
                // lower_bound: first idx with sx[idx] >= xc
                int lo = 0, hi = N;
                #pragma unroll 1
                while (lo < hi) {
                    int mid = (lo + hi) >> 1;
                    if (sx[mid] < xc) lo = mid + 1; else hi = mid;
                }
                int li = min(max(lo - 1, 0), N - 2);
                int hiI = min(lo, N - 1);
                float xl = sx[li], xh = sx[hiI];
                float denom = xh - xl;
                if (denom == 0.f) denom = 1.f;
                float w = (xc - xl) / (denom + 1e-9f);
                w = fminf(fmaxf(w, 0.f), 1.f);
                float a1 = __ldg(y1r + li), b1 = __ldg(y1r + hiI);
                float a2 = __ldg(y2r + li), b2 = __ldg(y2r + hiI);
                v1 = a1 + w * (b1 - a1);
                v2 = a2 + w * (b2 - a2);
            }
        }
        g_y1c[(size_t)b * MP + m] = __float2bfloat16(v1);
        g_y2c[(size_t)b * MP + m] = __float2bfloat16(v2);
        s1 += v1 * v1;
        s2 += v2 * v2;
    }

    #pragma unroll
    for (int o = 16; o > 0; o >>= 1) {
        s1 += __shfl_xor_sync(0xffffffffu, s1, o);
        s2 += __shfl_xor_sync(0xffffffffu, s2, o);
    }
    if ((tid & 31) == 0) { red1[tid >> 5] = s1; red2[tid >> 5] = s2; }
    __syncthreads();
    if (tid == 0) {
        float t1 = 0.f, t2 = 0.f;
        #pragma unroll
        for (int w = 0; w < 8; w++) { t1 += red1[w]; t2 += red2[w]; }
        g_sq1[b] = t1 * (1.0f / (float)M_C);
        g_sq2[b] = t2 * (1.0f / (float)M_C);
    }
}

// ---------------- kernel 3: bf16 tensor-core GEMM + fused loss epilogue ----
// C[i][j] = dot(y1c[i,:], y2c[j,:]) via mma.sync.m16n8k16.bf16 (fp32 accum).
// Block tile 128(M) x 64(N), BK=32, 8 warps (4x2), warp tile 32x32.
// 3-stage cp.async pipeline; smem rows padded to 80B -> conflict-free ldmatrix.
#define GBM 128
#define GBN 64
#define GBK 32
#define ROW_B 80                       // bytes per smem row (32 bf16 + pad)
#define SA_STAGE (GBM * ROW_B)         // 10240 B
#define SB_STAGE (GBN * ROW_B)         // 5120 B
#define NSTAGE 3
#define SB_BASE (NSTAGE * SA_STAGE)    // 30720
#define SMEM_TOT (SB_BASE + NSTAGE * SB_STAGE)  // 46080 B

__device__ __forceinline__ void cp16(uint32_t dst, const void* src) {
    asm volatile("cp.async.cg.shared.global [%0], [%1], 16;\n"
                 :: "r"(dst), "l"(src));
}
__device__ __forceinline__ void ldsm_x4(uint32_t addr, uint32_t& r0, uint32_t& r1,
                                        uint32_t& r2, uint32_t& r3) {
    asm volatile("ldmatrix.sync.aligned.m8n8.x4.shared.b16 {%0,%1,%2,%3}, [%4];\n"
                 : "=r"(r0), "=r"(r1), "=r"(r2), "=r"(r3) : "r"(addr));
}
__device__ __forceinline__ void mma16816(float* c, const uint32_t* a, const uint32_t* b) {
    asm volatile(
        "mma.sync.aligned.m16n8k16.row.col.f32.bf16.bf16.f32 "
        "{%0,%1,%2,%3}, {%4,%5,%6,%7}, {%8,%9}, {%0,%1,%2,%3};\n"
        : "+f"(c[0]), "+f"(c[1]), "+f"(c[2]), "+f"(c[3])
        : "r"(a[0]), "r"(a[1]), "r"(a[2]), "r"(a[3]), "r"(b[0]), "r"(b[1]));
}

__global__ __launch_bounds__(256, 1) void gemm_loss_kernel(float* __restrict__ out, int B) {
    __shared__ __align__(16) unsigned char smem[SMEM_TOT];
    const uint32_t smem_u = (uint32_t)__cvta_generic_to_shared(smem);

    const int tid  = threadIdx.x;
    const int warp = tid >> 5;
    const int lane = tid & 31;

    const __nv_bfloat16* Ag = g_y1c + (size_t)blockIdx.y * GBM * MP;
    const __nv_bfloat16* Bg = g_y2c + (size_t)blockIdx.x * GBN * MP;

    // global->smem chunk assignment (16B chunks; row = id/4, kchunk = id%4)
    const int a_row0 = tid >> 2, a_c = tid & 3;      // + second chunk at id+256

    const int nkb = MP / GBK;    // 94

    auto load_stage = [&](int st, int kb) {
        const int k0 = kb * GBK;
        // A: 512 chunks over 256 threads (2 each)
        cp16(smem_u + st * SA_STAGE + a_row0 * ROW_B + a_c * 16,
             Ag + (size_t)a_row0 * MP + k0 + a_c * 8);
        cp16(smem_u + st * SA_STAGE + (a_row0 + 64) * ROW_B + a_c * 16,
             Ag + (size_t)(a_row0 + 64) * MP + k0 + a_c * 8);
        // B: 256 chunks (1 each)
        cp16(smem_u + SB_BASE + st * SB_STAGE + a_row0 * ROW_B + a_c * 16,
             Bg + (size_t)a_row0 * MP + k0 + a_c * 8);
    };

    load_stage(0, 0); asm volatile("cp.async.commit_group;\n" ::);
    load_stage(1, 1); asm volatile("cp.async.commit_group;\n" ::);

    // warp tiling: 4 warps along M, 2 along N
    const int wm = (warp >> 1) * 32;
    const int wn = (warp & 1) * 32;
    const int lr = lane & 7, q = lane >> 3;

    // per-lane ldmatrix address components
    const uint32_t a_addr_base = smem_u + (wm + lr + (q & 1) * 8) * ROW_B + (q >> 1) * 16;
    const uint32_t b_addr_base = smem_u + SB_BASE + (wn + lr + (q >> 1) * 8) * ROW_B + (q & 1) * 16;

    float acc[2][4][4];
    #pragma unroll
    for (int mf = 0; mf < 2; mf++)
        #pragma unroll
        for (int nf = 0; nf < 4; nf++)
            #pragma unroll
            for (int r = 0; r < 4; r++) acc[mf][nf][r] = 0.f;

    for (int kb = 0; kb < nkb; kb++) {
        asm volatile("cp.async.wait_group 1;\n" ::);
        __syncthreads();
        if (kb + 2 < nkb) load_stage((kb + 2) % NSTAGE, kb + 2);
        asm volatile("cp.async.commit_group;\n" ::);

        const int st = kb % NSTAGE;
        const uint32_t aS = a_addr_base + st * SA_STAGE;
        const uint32_t bS = b_addr_base + st * SB_STAGE;

        #pragma unroll
        for (int s = 0; s < 2; s++) {      // two k16 sub-steps per BK=32
            uint32_t a[2][4], b[2][4];
            #pragma unroll
            for (int mf = 0; mf < 2; mf++)
                ldsm_x4(aS + (mf * 16) * ROW_B + s * 32,
                        a[mf][0], a[mf][1], a[mf][2], a[mf][3]);
            #pragma unroll
            for (int p = 0; p < 2; p++)
                ldsm_x4(bS + (p * 16) * ROW_B + s * 32,
                        b[p][0], b[p][1], b[p][2], b[p][3]);
            #pragma unroll
            for (int mf = 0; mf < 2; mf++)
                #pragma unroll
                for (int nf = 0; nf < 4; nf++) {
                    uint32_t bb[2] = { b[nf >> 1][(nf & 1) * 2],
                                       b[nf >> 1][(nf & 1) * 2 + 1] };
                    mma16816(acc[mf][nf], a[mf], bb);
                }
        }
        __syncthreads();
    }

    // fused loss epilogue
    const float inv_m = 1.0f / (float)M_C;
    const int gm = blockIdx.y * GBM + wm;
    const int gn = blockIdx.x * GBN + wn;
    #pragma unroll
    for (int mf = 0; mf < 2; mf++) {
        #pragma unroll
        for (int h = 0; h < 2; h++) {
            const int i = gm + mf * 16 + (lane >> 2) + h * 8;
            const float s1 = g_sq1[i];
            const float base = s1 + g_sq2[i] + EPS_B;   // reference quirk: both i-indexed
            const float scale = 2.0f / base;
            #pragma unroll
            for (int nf = 0; nf < 4; nf++) {
                const int j = gn + nf * 8 + (lane & 3) * 2;
                float c0 = acc[mf][nf][h * 2 + 0];
                float c1 = acc[mf][nf][h * 2 + 1];
                float d0 = fmaxf(s1 + g_sq2[j]     - 2.0f * c0 * inv_m, 0.f);
                float d1 = fmaxf(s1 + g_sq2[j + 1] - 2.0f * c1 * inv_m, 0.f);
                float2 o = { sqrtf(d0 * scale), sqrtf(d1 * scale) };
                *(float2*)(out + (size_t)i * B + j) = o;
            }
        }
    }
}

// ---------------- launch ----------------
extern "C" void kernel_launch(void* const* d_in, const int* in_sizes, int n_in,
                              void* d_out, int out_size) {
    const float* x  = (const float*)d_in[0];
    const float* y1 = (const float*)d_in[1];
    const float* y2 = (const float*)d_in[2];
    float* out = (float*)d_out;

    // out is [B, B] -> exact integer sqrt
    int B = 1;
    while ((long long)(B + 1) * (B + 1) <= (long long)out_size) B++;
    int N = in_sizes[0] / B;

    minmax_kernel<<<1, 1024>>>(x, B, N);
    interp_kernel<<<B, 256>>>(x, y1, y2, N);
    dim3 grid(B / GBN, B / GBM);   // (16, 8)
    gemm_loss_kernel<<<grid, 256>>>(out, B);
}